// round 11
// baseline (speedup 1.0000x reference)
#include <cuda_runtime.h>
#include <cuda_fp16.h>
#include <math.h>

// Problem constants
#define S_LEN 2048
#define D_MODEL 2048
#define NQ_HEADS 16
#define NKV_HEADS 2
#define HEAD_DIM 128
#define Q_SIZE (NQ_HEADS * HEAD_DIM)          // 2048
#define KV_SIZE (NKV_HEADS * HEAD_DIM)        // 256
#define QKV_COLS (Q_SIZE + 2 * KV_SIZE)       // 2560

// Scratch
__device__ float  g_qkv[S_LEN * QKV_COLS];                 // fp32 QKV output
__device__ __half g_hid_h[S_LEN * D_MODEL];                // hidden, f16
__device__ __half g_wqkv_t[QKV_COLS * D_MODEL];            // W_qkv^T [n][k] f16
__device__ __half g_wo_t[D_MODEL * Q_SIZE];                // W_o^T [n][k] f16
__device__ __half g_q_h[NQ_HEADS * S_LEN * HEAD_DIM];      // [h][s][d]
__device__ __half g_k_h[NKV_HEADS * S_LEN * HEAD_DIM];     // [kvh][s][d]
__device__ __half g_v_h[NKV_HEADS * S_LEN * HEAD_DIM];     // [kvh][s][d]
__device__ __half g_att_h[S_LEN * Q_SIZE];                 // attention out, f16

// ---------------------------------------------------------------------------
// helpers
// ---------------------------------------------------------------------------
__device__ __forceinline__ void mma_f16(float c[4], const unsigned a[4],
                                        unsigned b0, unsigned b1)
{
    asm volatile(
        "mma.sync.aligned.m16n8k16.row.col.f32.f16.f16.f32 "
        "{%0,%1,%2,%3}, {%4,%5,%6,%7}, {%8,%9}, {%0,%1,%2,%3};"
        : "+f"(c[0]), "+f"(c[1]), "+f"(c[2]), "+f"(c[3])
        : "r"(a[0]), "r"(a[1]), "r"(a[2]), "r"(a[3]), "r"(b0), "r"(b1));
}

__device__ __forceinline__ void ldsm4(unsigned r[4], unsigned addr) {
    asm volatile("ldmatrix.sync.aligned.m8n8.x4.shared.b16 {%0,%1,%2,%3}, [%4];"
        : "=r"(r[0]), "=r"(r[1]), "=r"(r[2]), "=r"(r[3]) : "r"(addr));
}
__device__ __forceinline__ void ldsm4t(unsigned r[4], unsigned addr) {
    asm volatile("ldmatrix.sync.aligned.m8n8.x4.trans.shared.b16 {%0,%1,%2,%3}, [%4];"
        : "=r"(r[0]), "=r"(r[1]), "=r"(r[2]), "=r"(r[3]) : "r"(addr));
}

__device__ __forceinline__ unsigned packh2(float lo, float hi) {
    __half2 h = __floats2half2_rn(lo, hi);
    return *reinterpret_cast<unsigned*>(&h);
}

__device__ __forceinline__ void cp_async16(void* smem_dst, const void* gmem_src) {
    unsigned d = (unsigned)__cvta_generic_to_shared(smem_dst);
    asm volatile("cp.async.cg.shared.global [%0], [%1], 16;\n" :: "r"(d), "l"(gmem_src));
}
__device__ __forceinline__ void cp_commit() {
    asm volatile("cp.async.commit_group;\n");
}
template <int N>
__device__ __forceinline__ void cp_wait() {
    asm volatile("cp.async.wait_group %0;\n" :: "n"(N));
}

// ---------------------------------------------------------------------------
// Prepass: fp32 -> fp16
// ---------------------------------------------------------------------------
__global__ void cvt_f16_kernel(const float* __restrict__ src,
                               __half* __restrict__ dst, int n4)
{
    for (int i = blockIdx.x * blockDim.x + threadIdx.x; i < n4;
         i += gridDim.x * blockDim.x) {
        float4 v = ((const float4*)src)[i];
        ((__half2*)dst)[i * 2]     = __floats2half2_rn(v.x, v.y);
        ((__half2*)dst)[i * 2 + 1] = __floats2half2_rn(v.z, v.w);
    }
}

// Transpose + cvt: src [R][C] f32 -> dst [C][R] f16
__global__ void transpose_cvt_kernel(const float* __restrict__ src,
                                     __half* __restrict__ dst, int R, int C)
{
    __shared__ float t[32][33];
    int r0 = blockIdx.y * 32, c0 = blockIdx.x * 32;
    int x = threadIdx.x, y = threadIdx.y;   // 32 x 8
    #pragma unroll
    for (int i = y; i < 32; i += 8)
        t[i][x] = src[(size_t)(r0 + i) * C + c0 + x];
    __syncthreads();
    #pragma unroll
    for (int i = y; i < 32; i += 8)
        dst[(size_t)(c0 + i) * R + r0 + x] = __float2half_rn(t[x][i]);
}

// ---------------------------------------------------------------------------
// f16 GEMM: C[M,N] = A[M,K] @ Bt[N,K]^T (+bias). 256x128x64 tiles, 512 thr
// (16 warps, 4Mx4N, warp tile 64x32), 3-stage cp.async, ldmatrix + m16n8k16.
// ---------------------------------------------------------------------------
#define GBM 256
#define GBN 128
#define GBK 64
#define SH 72                         // row stride in halves (144B; 16i mod 128 distinct)
#define GA_H (GBM * SH)               // 18432 halves
#define GB_H (GBN * SH)               // 9216 halves
#define STAGE_H (GA_H + GB_H)         // 27648 halves = 55296 B
#define NSTAGE 3
#define GEMM_SMEM_BYTES (NSTAGE * STAGE_H * 2)   // 165888 B

__global__ void __launch_bounds__(512) gemm_f16_kernel(
    const __half* __restrict__ A, const __half* __restrict__ Bt,
    const float* __restrict__ bias, float* __restrict__ C,
    int M, int N, int K)
{
    extern __shared__ __half smh[];

    const int tid = threadIdx.x;
    const int wid = tid >> 5, lane = tid & 31;
    const int g = lane >> 2, tg = lane & 3;
    const int quad = lane >> 3, lr = lane & 7;
    const int bm = blockIdx.y * GBM, bn = blockIdx.x * GBN;
    const int wm = (wid >> 2) * 64, wn = (wid & 3) * 32;

    const int rowoff = (quad & 1) * 8 + lr;
    const int coloff = (quad >> 1) * 8;

    const int ld_r = tid >> 3;            // 0..63 (plus p*64)
    const int ld_c = (tid & 7) * 8;       // halves, 0..56

    const int KT = K / GBK;

    auto issue = [&](int s, int kt) {
        __half* As = smh + s * STAGE_H;
        __half* Bs = As + GA_H;
        int k0 = kt * GBK;
        #pragma unroll
        for (int p = 0; p < 4; p++) {
            int r = p * 64 + ld_r;        // 0..255
            cp_async16(&As[r * SH + ld_c], &A[(size_t)(bm + r) * K + k0 + ld_c]);
        }
        #pragma unroll
        for (int p = 0; p < 2; p++) {
            int r = p * 64 + ld_r;        // 0..127
            cp_async16(&Bs[r * SH + ld_c], &Bt[(size_t)(bn + r) * K + k0 + ld_c]);
        }
    };

    float acc[4][4][4];
    #pragma unroll
    for (int mt = 0; mt < 4; mt++)
        #pragma unroll
        for (int nt = 0; nt < 4; nt++)
            #pragma unroll
            for (int i = 0; i < 4; i++) acc[mt][nt][i] = 0.f;

    issue(0, 0); cp_commit();
    issue(1, 1); cp_commit();

    for (int kt = 0; kt < KT; kt++) {
        cp_wait<1>();
        __syncthreads();
        if (kt + 2 < KT) issue((kt + 2) % NSTAGE, kt + 2);
        cp_commit();

        unsigned sA = (unsigned)__cvta_generic_to_shared(
                          smh + (kt % NSTAGE) * STAGE_H);
        unsigned sB = sA + GA_H * 2;
        unsigned aBase = sA + ((wm + rowoff) * SH + coloff) * 2;
        unsigned bBase = sB + ((wn + rowoff) * SH + coloff) * 2;

        #pragma unroll
        for (int kk = 0; kk < GBK; kk += 16) {
            unsigned a[4][4], b0[4], b1[4];
            #pragma unroll
            for (int mt = 0; mt < 4; mt++)
                ldsm4(a[mt], aBase + (mt * 16 * SH + kk) * 2);
            ldsm4(b0, bBase + kk * 2);
            ldsm4(b1, bBase + (16 * SH + kk) * 2);
            #pragma unroll
            for (int mt = 0; mt < 4; mt++) {
                mma_f16(acc[mt][0], a[mt], b0[0], b0[2]);
                mma_f16(acc[mt][1], a[mt], b0[1], b0[3]);
                mma_f16(acc[mt][2], a[mt], b1[0], b1[2]);
                mma_f16(acc[mt][3], a[mt], b1[1], b1[3]);
            }
        }
        // next-iteration top barrier protects this stage from refill
    }

    #pragma unroll
    for (int mt = 0; mt < 4; mt++) {
        #pragma unroll
        for (int nt = 0; nt < 4; nt++) {
            int row = bm + wm + mt * 16 + g;
            int col = bn + wn + nt * 8 + tg * 2;
            float b0 = 0.f, b1 = 0.f;
            if (bias) { b0 = bias[col]; b1 = bias[col + 1]; }
            *(float2*)&C[(size_t)row * N + col] =
                make_float2(acc[mt][nt][0] + b0, acc[mt][nt][1] + b1);
            *(float2*)&C[(size_t)(row + 8) * N + col] =
                make_float2(acc[mt][nt][2] + b0, acc[mt][nt][3] + b1);
        }
    }
}

// ---------------------------------------------------------------------------
// RoPE + split + scale; outputs f16
// ---------------------------------------------------------------------------
__global__ void __launch_bounds__(256) rope_split_kernel(
    const float* __restrict__ cosT, const float* __restrict__ sinT)
{
    const int s = blockIdx.x;
    const float* row = g_qkv + (size_t)s * QKV_COLS;
    const float scale = 0.08838834764831845f;   // 128^-0.5

    for (int idx = threadIdx.x; idx < NQ_HEADS * 64; idx += blockDim.x) {
        int h = idx >> 6, d = idx & 63;
        float x1 = row[h * HEAD_DIM + d];
        float x2 = row[h * HEAD_DIM + d + 64];
        float c  = cosT[s * 64 + d];
        float sn = sinT[s * 64 + d];
        __half* qrow = g_q_h + ((size_t)h * S_LEN + s) * HEAD_DIM;
        qrow[d]      = __float2half_rn((x1 * c - x2 * sn) * scale);
        qrow[d + 64] = __float2half_rn((x1 * sn + x2 * c) * scale);
    }
    for (int idx = threadIdx.x; idx < NKV_HEADS * 64; idx += blockDim.x) {
        int h = idx >> 6, d = idx & 63;
        float x1 = row[Q_SIZE + h * HEAD_DIM + d];
        float x2 = row[Q_SIZE + h * HEAD_DIM + d + 64];
        float c  = cosT[s * 64 + d];
        float sn = sinT[s * 64 + d];
        __half* krow = g_k_h + ((size_t)h * S_LEN + s) * HEAD_DIM;
        krow[d]      = __float2half_rn(x1 * c - x2 * sn);
        krow[d + 64] = __float2half_rn(x1 * sn + x2 * c);
    }
    for (int idx = threadIdx.x; idx < NKV_HEADS * HEAD_DIM; idx += blockDim.x) {
        int h = idx >> 7, d = idx & 127;
        g_v_h[((size_t)h * S_LEN + s) * HEAD_DIM + d] =
            __float2half_rn(row[Q_SIZE + KV_SIZE + h * HEAD_DIM + d]);
    }
}

// ---------------------------------------------------------------------------
// Flash attention, f16 HMMA. 8 warps, 128 q-rows/CTA, KV tile 64 (2 bufs).
// P stays in registers (C-frag == A-frag layout). K via ldsm4, V via ldsm4t.
// ---------------------------------------------------------------------------
#define SA 136
#define Q_HH (128 * SA)
#define KV_HH (64 * SA)
#define FA_SMEM_BYTES ((Q_HH + 4 * KV_HH) * 2)   // 104448 B

__global__ void __launch_bounds__(256, 2) flash_attn_f16_kernel()
{
    extern __shared__ __half smh[];
    __half* Qs = smh;

    const int qb = gridDim.x - 1 - blockIdx.x;   // heavy blocks first
    const int h  = blockIdx.y;
    const int kvh = h >> 3;
    const int tid = threadIdx.x;
    const int wid = tid >> 5, lane = tid & 31;
    const int g = lane >> 2, tg = lane & 3;
    const int quad = lane >> 3, lr = lane & 7;
    const int m0 = wid * 16;

    const int rowoff = (quad & 1) * 8 + lr;
    const int coloff = (quad >> 1) * 8;

    const __half* qg = g_q_h + ((size_t)h * S_LEN + qb * 128) * HEAD_DIM;
    #pragma unroll
    for (int p = 0; p < 8; p++) {
        int idx = p * 256 + tid;
        int r = idx >> 4, ch = (idx & 15) * 8;
        cp_async16(&Qs[r * SA + ch], &qg[(size_t)r * HEAD_DIM + ch]);
    }
    cp_commit();

    auto issueKV = [&](int jb, int b) {
        __half* Ks = smh + Q_HH + b * 2 * KV_HH;
        __half* Vs = Ks + KV_HH;
        const __half* kg = g_k_h + ((size_t)kvh * S_LEN + jb * 64) * HEAD_DIM;
        const __half* vg = g_v_h + ((size_t)kvh * S_LEN + jb * 64) * HEAD_DIM;
        #pragma unroll
        for (int p = 0; p < 4; p++) {
            int idx = p * 256 + tid;
            int r = idx >> 4, ch = (idx & 15) * 8;
            cp_async16(&Ks[r * SA + ch], &kg[(size_t)r * HEAD_DIM + ch]);
            cp_async16(&Vs[r * SA + ch], &vg[(size_t)r * HEAD_DIM + ch]);
        }
    };

    const int jb_end = 2 * qb + 2;
    issueKV(0, 0); cp_commit();

    float m_i[2] = { -1e30f, -1e30f };
    float l_i[2] = { 0.f, 0.f };
    float o[16][4];
    #pragma unroll
    for (int dt = 0; dt < 16; dt++)
        #pragma unroll
        for (int i = 0; i < 4; i++) o[dt][i] = 0.f;

    unsigned sQ = (unsigned)__cvta_generic_to_shared(Qs);
    unsigned qBase = sQ + ((m0 + rowoff) * SA + coloff) * 2;

    int buf = 0;
    for (int jb = 0; jb < jb_end; jb++) {
        cp_wait<0>();
        __syncthreads();
        if (jb + 1 < jb_end) issueKV(jb + 1, buf ^ 1);
        cp_commit();

        if (jb * 64 <= qb * 128 + m0 + 15) {
            unsigned sK = (unsigned)__cvta_generic_to_shared(
                              smh + Q_HH + buf * 2 * KV_HH);
            unsigned sV = sK + KV_HH * 2;
            unsigned kBase = sK + (rowoff * SA + coloff) * 2;
            unsigned vBase = sV + ((coloff + lr) * SA + (quad & 1) * 8) * 2;

            float sc[8][4];
            #pragma unroll
            for (int nt = 0; nt < 8; nt++)
                #pragma unroll
                for (int i = 0; i < 4; i++) sc[nt][i] = 0.f;

            #pragma unroll
            for (int kk = 0; kk < HEAD_DIM; kk += 16) {
                unsigned qa[4];
                ldsm4(qa, qBase + kk * 2);
                #pragma unroll
                for (int p = 0; p < 4; p++) {
                    unsigned kb[4];
                    ldsm4(kb, kBase + (p * 16 * SA + kk) * 2);
                    mma_f16(sc[p * 2],     qa, kb[0], kb[2]);
                    mma_f16(sc[p * 2 + 1], qa, kb[1], kb[3]);
                }
            }

            const int qr0 = qb * 128 + m0 + g;
            const int qr1 = qr0 + 8;
            if (jb * 64 + 63 > qr0) {
                #pragma unroll
                for (int nt = 0; nt < 8; nt++) {
                    #pragma unroll
                    for (int c = 0; c < 2; c++) {
                        int col = jb * 64 + nt * 8 + tg * 2 + c;
                        if (col > qr0) sc[nt][c]     = -1e30f;
                        if (col > qr1) sc[nt][2 + c] = -1e30f;
                    }
                }
            }

            float mx0 = -1e30f, mx1 = -1e30f;
            #pragma unroll
            for (int nt = 0; nt < 8; nt++) {
                mx0 = fmaxf(mx0, fmaxf(sc[nt][0], sc[nt][1]));
                mx1 = fmaxf(mx1, fmaxf(sc[nt][2], sc[nt][3]));
            }
            mx0 = fmaxf(mx0, __shfl_xor_sync(0xffffffffu, mx0, 1));
            mx0 = fmaxf(mx0, __shfl_xor_sync(0xffffffffu, mx0, 2));
            mx1 = fmaxf(mx1, __shfl_xor_sync(0xffffffffu, mx1, 1));
            mx1 = fmaxf(mx1, __shfl_xor_sync(0xffffffffu, mx1, 2));

            float mn0 = fmaxf(m_i[0], mx0);
            float mn1 = fmaxf(m_i[1], mx1);
            float corr0 = __expf(m_i[0] - mn0);
            float corr1 = __expf(m_i[1] - mn1);
            float ps0 = 0.f, ps1 = 0.f;
            #pragma unroll
            for (int nt = 0; nt < 8; nt++) {
                sc[nt][0] = __expf(sc[nt][0] - mn0);
                sc[nt][1] = __expf(sc[nt][1] - mn0);
                sc[nt][2] = __expf(sc[nt][2] - mn1);
                sc[nt][3] = __expf(sc[nt][3] - mn1);
                ps0 += sc[nt][0] + sc[nt][1];
                ps1 += sc[nt][2] + sc[nt][3];
            }
            ps0 += __shfl_xor_sync(0xffffffffu, ps0, 1);
            ps0 += __shfl_xor_sync(0xffffffffu, ps0, 2);
            ps1 += __shfl_xor_sync(0xffffffffu, ps1, 1);
            ps1 += __shfl_xor_sync(0xffffffffu, ps1, 2);
            l_i[0] = l_i[0] * corr0 + ps0;
            l_i[1] = l_i[1] * corr1 + ps1;
            m_i[0] = mn0;
            m_i[1] = mn1;

            #pragma unroll
            for (int dt = 0; dt < 16; dt++) {
                o[dt][0] *= corr0;
                o[dt][1] *= corr0;
                o[dt][2] *= corr1;
                o[dt][3] *= corr1;
            }

            unsigned pa[4][4];
            #pragma unroll
            for (int t = 0; t < 4; t++) {
                pa[t][0] = packh2(sc[2 * t][0],     sc[2 * t][1]);
                pa[t][1] = packh2(sc[2 * t][2],     sc[2 * t][3]);
                pa[t][2] = packh2(sc[2 * t + 1][0], sc[2 * t + 1][1]);
                pa[t][3] = packh2(sc[2 * t + 1][2], sc[2 * t + 1][3]);
            }

            #pragma unroll
            for (int t = 0; t < 4; t++) {
                #pragma unroll
                for (int p2 = 0; p2 < 8; p2++) {
                    unsigned vb[4];
                    ldsm4t(vb, vBase + (t * 16 * SA + p2 * 16) * 2);
                    mma_f16(o[p2 * 2],     pa[t], vb[0], vb[2]);
                    mma_f16(o[p2 * 2 + 1], pa[t], vb[1], vb[3]);
                }
            }
        }
        buf ^= 1;
    }

    float inv0 = 1.f / l_i[0];
    float inv1 = 1.f / l_i[1];
    int r0 = qb * 128 + m0 + g;
    int r1 = r0 + 8;
    #pragma unroll
    for (int dt = 0; dt < 16; dt++) {
        int d = dt * 8 + tg * 2;
        *(__half2*)&g_att_h[(size_t)r0 * Q_SIZE + h * HEAD_DIM + d] =
            __floats2half2_rn(o[dt][0] * inv0, o[dt][1] * inv0);
        *(__half2*)&g_att_h[(size_t)r1 * Q_SIZE + h * HEAD_DIM + d] =
            __floats2half2_rn(o[dt][2] * inv1, o[dt][3] * inv1);
    }
}

// ---------------------------------------------------------------------------
// Launch
// ---------------------------------------------------------------------------
extern "C" void kernel_launch(void* const* d_in, const int* in_sizes, int n_in,
                              void* d_out, int out_size)
{
    const float* hidden = (const float*)d_in[0];
    const float* cosT   = (const float*)d_in[1];
    const float* sinT   = (const float*)d_in[2];
    const float* W_qkv  = (const float*)d_in[7];
    const float* b_qkv  = (const float*)d_in[8];
    const float* W_o    = (const float*)d_in[9];
    float* out = (float*)d_out;

    float* qkv_p;
    __half *hid_p, *wqkv_p, *wo_p, *att_p;
    cudaGetSymbolAddress((void**)&qkv_p,  g_qkv);
    cudaGetSymbolAddress((void**)&hid_p,  g_hid_h);
    cudaGetSymbolAddress((void**)&wqkv_p, g_wqkv_t);
    cudaGetSymbolAddress((void**)&wo_p,   g_wo_t);
    cudaGetSymbolAddress((void**)&att_p,  g_att_h);

    cudaFuncSetAttribute(gemm_f16_kernel,
                         cudaFuncAttributeMaxDynamicSharedMemorySize,
                         GEMM_SMEM_BYTES);
    cudaFuncSetAttribute(flash_attn_f16_kernel,
                         cudaFuncAttributeMaxDynamicSharedMemorySize,
                         FA_SMEM_BYTES);

    // 0) fp32 -> fp16 prepass (+ weight transposes to [n][k])
    cvt_f16_kernel<<<1184, 256>>>(hidden, hid_p, S_LEN * D_MODEL / 4);
    {
        dim3 grid(QKV_COLS / 32, D_MODEL / 32);
        transpose_cvt_kernel<<<grid, dim3(32, 8)>>>(W_qkv, wqkv_p,
                                                    D_MODEL, QKV_COLS);
    }
    {
        dim3 grid(D_MODEL / 32, Q_SIZE / 32);
        transpose_cvt_kernel<<<grid, dim3(32, 8)>>>(W_o, wo_p,
                                                    Q_SIZE, D_MODEL);
    }

    // 1) QKV projection + bias (fp32 out)
    {
        dim3 grid(QKV_COLS / GBN, S_LEN / GBM);   // 20 x 8 = 160 CTAs
        gemm_f16_kernel<<<grid, 512, GEMM_SMEM_BYTES>>>(
            hid_p, wqkv_p, b_qkv, qkv_p, S_LEN, QKV_COLS, D_MODEL);
    }
    // 2) RoPE + split + q-scale (f16 out)
    rope_split_kernel<<<S_LEN, 256>>>(cosT, sinT);
    // 3) Causal GQA flash attention (f16 HMMA)
    {
        dim3 grid(S_LEN / 128, NQ_HEADS);
        flash_attn_f16_kernel<<<grid, 256, FA_SMEM_BYTES>>>();
    }
    // 4) Output projection (fp32 out)
    {
        dim3 grid(D_MODEL / GBN, S_LEN / GBM);    // 16 x 8 = 128 CTAs (1 wave)
        gemm_f16_kernel<<<grid, 512, GEMM_SMEM_BYTES>>>(
            att_p, wo_p, nullptr, out, S_LEN, D_MODEL, Q_SIZE);
    }
}

// round 12
// speedup vs baseline: 1.0840x; 1.0840x over previous
#include <cuda_runtime.h>
#include <cuda_fp16.h>
#include <math.h>

// Problem constants
#define S_LEN 2048
#define D_MODEL 2048
#define NQ_HEADS 16
#define NKV_HEADS 2
#define HEAD_DIM 128
#define Q_SIZE (NQ_HEADS * HEAD_DIM)          // 2048
#define KV_SIZE (NKV_HEADS * HEAD_DIM)        // 256
#define QKV_COLS (Q_SIZE + 2 * KV_SIZE)       // 2560

// Scratch
__device__ float  g_qkv[S_LEN * QKV_COLS];                 // fp32 QKV output
__device__ __half g_hid_h[S_LEN * D_MODEL];                // hidden, f16
__device__ __half g_wqkv_t[QKV_COLS * D_MODEL];            // W_qkv^T [n][k] f16
__device__ __half g_wo_t[D_MODEL * Q_SIZE];                // W_o^T [n][k] f16
__device__ __half g_q_h[NQ_HEADS * S_LEN * HEAD_DIM];      // [h][s][d]
__device__ __half g_k_h[NKV_HEADS * S_LEN * HEAD_DIM];     // [kvh][s][d]
__device__ __half g_v_h[NKV_HEADS * S_LEN * HEAD_DIM];     // [kvh][s][d]
__device__ __half g_att_h[S_LEN * Q_SIZE];                 // attention out, f16

// ---------------------------------------------------------------------------
// helpers
// ---------------------------------------------------------------------------
__device__ __forceinline__ void mma_f16(float c[4], const unsigned a[4],
                                        unsigned b0, unsigned b1)
{
    asm volatile(
        "mma.sync.aligned.m16n8k16.row.col.f32.f16.f16.f32 "
        "{%0,%1,%2,%3}, {%4,%5,%6,%7}, {%8,%9}, {%0,%1,%2,%3};"
        : "+f"(c[0]), "+f"(c[1]), "+f"(c[2]), "+f"(c[3])
        : "r"(a[0]), "r"(a[1]), "r"(a[2]), "r"(a[3]), "r"(b0), "r"(b1));
}

__device__ __forceinline__ void ldsm4(unsigned r[4], unsigned addr) {
    asm volatile("ldmatrix.sync.aligned.m8n8.x4.shared.b16 {%0,%1,%2,%3}, [%4];"
        : "=r"(r[0]), "=r"(r[1]), "=r"(r[2]), "=r"(r[3]) : "r"(addr));
}
__device__ __forceinline__ void ldsm4t(unsigned r[4], unsigned addr) {
    asm volatile("ldmatrix.sync.aligned.m8n8.x4.trans.shared.b16 {%0,%1,%2,%3}, [%4];"
        : "=r"(r[0]), "=r"(r[1]), "=r"(r[2]), "=r"(r[3]) : "r"(addr));
}

__device__ __forceinline__ unsigned packh2(float lo, float hi) {
    __half2 h = __floats2half2_rn(lo, hi);
    return *reinterpret_cast<unsigned*>(&h);
}

__device__ __forceinline__ void cp_async16(void* smem_dst, const void* gmem_src) {
    unsigned d = (unsigned)__cvta_generic_to_shared(smem_dst);
    asm volatile("cp.async.cg.shared.global [%0], [%1], 16;\n" :: "r"(d), "l"(gmem_src));
}
__device__ __forceinline__ void cp_commit() {
    asm volatile("cp.async.commit_group;\n");
}
template <int N>
__device__ __forceinline__ void cp_wait() {
    asm volatile("cp.async.wait_group %0;\n" :: "n"(N));
}

// ---------------------------------------------------------------------------
// Prepass: fp32 -> fp16
// ---------------------------------------------------------------------------
__global__ void cvt_f16_kernel(const float* __restrict__ src,
                               __half* __restrict__ dst, int n4)
{
    for (int i = blockIdx.x * blockDim.x + threadIdx.x; i < n4;
         i += gridDim.x * blockDim.x) {
        float4 v = ((const float4*)src)[i];
        ((__half2*)dst)[i * 2]     = __floats2half2_rn(v.x, v.y);
        ((__half2*)dst)[i * 2 + 1] = __floats2half2_rn(v.z, v.w);
    }
}

// Transpose + cvt: src [R][C] f32 -> dst [C][R] f16
__global__ void transpose_cvt_kernel(const float* __restrict__ src,
                                     __half* __restrict__ dst, int R, int C)
{
    __shared__ float t[32][33];
    int r0 = blockIdx.y * 32, c0 = blockIdx.x * 32;
    int x = threadIdx.x, y = threadIdx.y;   // 32 x 8
    #pragma unroll
    for (int i = y; i < 32; i += 8)
        t[i][x] = src[(size_t)(r0 + i) * C + c0 + x];
    __syncthreads();
    #pragma unroll
    for (int i = y; i < 32; i += 8)
        dst[(size_t)(c0 + i) * R + r0 + x] = __float2half_rn(t[x][i]);
}

// ---------------------------------------------------------------------------
// f16 GEMM: C[M,N] = A[M,K] @ Bt[N,K]^T (+bias). 128x128x64 tiles, 256 thr
// (8 warps, 2Mx4N, warp tile 64x32), 2-stage cp.async, register
// double-buffered ldmatrix fragments, m16n8k16 HMMA.
// ---------------------------------------------------------------------------
#define GBM 128
#define GBN 128
#define GBK 64
#define SH 72                         // row stride in halves (144B; 16i mod 128 distinct)
#define GA_H (GBM * SH)               // 9216 halves
#define GB_H (GBN * SH)               // 9216 halves
#define STAGE_H (GA_H + GB_H)         // 18432 halves = 36864 B
#define NSTAGE 2
#define GEMM_SMEM_BYTES (NSTAGE * STAGE_H * 2)   // 73728 B

__global__ void __launch_bounds__(256, 2) gemm_f16_kernel(
    const __half* __restrict__ A, const __half* __restrict__ Bt,
    const float* __restrict__ bias, float* __restrict__ C,
    int M, int N, int K)
{
    extern __shared__ __half smh[];

    const int tid = threadIdx.x;
    const int wid = tid >> 5, lane = tid & 31;
    const int g = lane >> 2, tg = lane & 3;
    const int quad = lane >> 3, lr = lane & 7;
    const int bm = blockIdx.y * GBM, bn = blockIdx.x * GBN;
    const int wm = (wid >> 2) * 64, wn = (wid & 3) * 32;

    const int rowoff = (quad & 1) * 8 + lr;
    const int coloff = (quad >> 1) * 8;

    const int ld_r = tid >> 3;            // 0..31 (plus p*32)
    const int ld_c = (tid & 7) * 8;       // halves, 0..56

    const int KT = K / GBK;

    auto issue = [&](int s, int kt) {
        __half* As = smh + s * STAGE_H;
        __half* Bs = As + GA_H;
        int k0 = kt * GBK;
        #pragma unroll
        for (int p = 0; p < 4; p++) {
            int r = p * 32 + ld_r;        // 0..127
            cp_async16(&As[r * SH + ld_c], &A[(size_t)(bm + r) * K + k0 + ld_c]);
            cp_async16(&Bs[r * SH + ld_c], &Bt[(size_t)(bn + r) * K + k0 + ld_c]);
        }
    };

    float acc[4][4][4];
    #pragma unroll
    for (int mt = 0; mt < 4; mt++)
        #pragma unroll
        for (int nt = 0; nt < 4; nt++)
            #pragma unroll
            for (int i = 0; i < 4; i++) acc[mt][nt][i] = 0.f;

    issue(0, 0); cp_commit();

    for (int kt = 0; kt < KT; kt++) {
        cp_wait<0>();
        __syncthreads();   // stage kt ready; all warps done with buffer (kt+1)&1
        if (kt + 1 < KT) issue((kt + 1) & 1, kt + 1);
        cp_commit();

        unsigned sA = (unsigned)__cvta_generic_to_shared(
                          smh + (kt & 1) * STAGE_H);
        unsigned sB = sA + GA_H * 2;
        unsigned aBase = sA + ((wm + rowoff) * SH + coloff) * 2;
        unsigned bBase = sB + ((wn + rowoff) * SH + coloff) * 2;

        // register double-buffered fragments across the 4 kk-steps
        unsigned a[2][4][4], b0[2][4], b1[2][4];
        #pragma unroll
        for (int mt = 0; mt < 4; mt++)
            ldsm4(a[0][mt], aBase + (mt * 16 * SH) * 2);
        ldsm4(b0[0], bBase);
        ldsm4(b1[0], bBase + (16 * SH) * 2);

        #pragma unroll
        for (int s2 = 0; s2 < 4; s2++) {
            const int cur = s2 & 1, nxt = cur ^ 1;
            const int kk = (s2 + 1) * 16;
            if (s2 < 3) {
                #pragma unroll
                for (int mt = 0; mt < 4; mt++)
                    ldsm4(a[nxt][mt], aBase + (mt * 16 * SH + kk) * 2);
                ldsm4(b0[nxt], bBase + kk * 2);
                ldsm4(b1[nxt], bBase + (16 * SH + kk) * 2);
            }
            #pragma unroll
            for (int mt = 0; mt < 4; mt++) {
                mma_f16(acc[mt][0], a[cur][mt], b0[cur][0], b0[cur][2]);
                mma_f16(acc[mt][1], a[cur][mt], b0[cur][1], b0[cur][3]);
                mma_f16(acc[mt][2], a[cur][mt], b1[cur][0], b1[cur][2]);
                mma_f16(acc[mt][3], a[cur][mt], b1[cur][1], b1[cur][3]);
            }
        }
        // next iteration's top barrier seals this buffer before refill
    }

    #pragma unroll
    for (int mt = 0; mt < 4; mt++) {
        #pragma unroll
        for (int nt = 0; nt < 4; nt++) {
            int row = bm + wm + mt * 16 + g;
            int col = bn + wn + nt * 8 + tg * 2;
            float b0 = 0.f, b1 = 0.f;
            if (bias) { b0 = bias[col]; b1 = bias[col + 1]; }
            *(float2*)&C[(size_t)row * N + col] =
                make_float2(acc[mt][nt][0] + b0, acc[mt][nt][1] + b1);
            *(float2*)&C[(size_t)(row + 8) * N + col] =
                make_float2(acc[mt][nt][2] + b0, acc[mt][nt][3] + b1);
        }
    }
}

// ---------------------------------------------------------------------------
// RoPE + split + scale; outputs f16
// ---------------------------------------------------------------------------
__global__ void __launch_bounds__(256) rope_split_kernel(
    const float* __restrict__ cosT, const float* __restrict__ sinT)
{
    const int s = blockIdx.x;
    const float* row = g_qkv + (size_t)s * QKV_COLS;
    const float scale = 0.08838834764831845f;   // 128^-0.5

    for (int idx = threadIdx.x; idx < NQ_HEADS * 64; idx += blockDim.x) {
        int h = idx >> 6, d = idx & 63;
        float x1 = row[h * HEAD_DIM + d];
        float x2 = row[h * HEAD_DIM + d + 64];
        float c  = cosT[s * 64 + d];
        float sn = sinT[s * 64 + d];
        __half* qrow = g_q_h + ((size_t)h * S_LEN + s) * HEAD_DIM;
        qrow[d]      = __float2half_rn((x1 * c - x2 * sn) * scale);
        qrow[d + 64] = __float2half_rn((x1 * sn + x2 * c) * scale);
    }
    for (int idx = threadIdx.x; idx < NKV_HEADS * 64; idx += blockDim.x) {
        int h = idx >> 6, d = idx & 63;
        float x1 = row[Q_SIZE + h * HEAD_DIM + d];
        float x2 = row[Q_SIZE + h * HEAD_DIM + d + 64];
        float c  = cosT[s * 64 + d];
        float sn = sinT[s * 64 + d];
        __half* krow = g_k_h + ((size_t)h * S_LEN + s) * HEAD_DIM;
        krow[d]      = __float2half_rn(x1 * c - x2 * sn);
        krow[d + 64] = __float2half_rn(x1 * sn + x2 * c);
    }
    for (int idx = threadIdx.x; idx < NKV_HEADS * HEAD_DIM; idx += blockDim.x) {
        int h = idx >> 7, d = idx & 127;
        g_v_h[((size_t)h * S_LEN + s) * HEAD_DIM + d] =
            __float2half_rn(row[Q_SIZE + KV_SIZE + h * HEAD_DIM + d]);
    }
}

// ---------------------------------------------------------------------------
// Flash attention, f16 HMMA. 8 warps, 128 q-rows/CTA, KV tile 64 (2 bufs).
// P stays in registers (C-frag == A-frag layout). K via ldsm4, V via ldsm4t.
// ---------------------------------------------------------------------------
#define SA 136
#define Q_HH (128 * SA)
#define KV_HH (64 * SA)
#define FA_SMEM_BYTES ((Q_HH + 4 * KV_HH) * 2)   // 104448 B

__global__ void __launch_bounds__(256, 2) flash_attn_f16_kernel()
{
    extern __shared__ __half smh[];
    __half* Qs = smh;

    const int qb = gridDim.x - 1 - blockIdx.x;   // heavy blocks first
    const int h  = blockIdx.y;
    const int kvh = h >> 3;
    const int tid = threadIdx.x;
    const int wid = tid >> 5, lane = tid & 31;
    const int g = lane >> 2, tg = lane & 3;
    const int quad = lane >> 3, lr = lane & 7;
    const int m0 = wid * 16;

    const int rowoff = (quad & 1) * 8 + lr;
    const int coloff = (quad >> 1) * 8;

    const __half* qg = g_q_h + ((size_t)h * S_LEN + qb * 128) * HEAD_DIM;
    #pragma unroll
    for (int p = 0; p < 8; p++) {
        int idx = p * 256 + tid;
        int r = idx >> 4, ch = (idx & 15) * 8;
        cp_async16(&Qs[r * SA + ch], &qg[(size_t)r * HEAD_DIM + ch]);
    }
    cp_commit();

    auto issueKV = [&](int jb, int b) {
        __half* Ks = smh + Q_HH + b * 2 * KV_HH;
        __half* Vs = Ks + KV_HH;
        const __half* kg = g_k_h + ((size_t)kvh * S_LEN + jb * 64) * HEAD_DIM;
        const __half* vg = g_v_h + ((size_t)kvh * S_LEN + jb * 64) * HEAD_DIM;
        #pragma unroll
        for (int p = 0; p < 4; p++) {
            int idx = p * 256 + tid;
            int r = idx >> 4, ch = (idx & 15) * 8;
            cp_async16(&Ks[r * SA + ch], &kg[(size_t)r * HEAD_DIM + ch]);
            cp_async16(&Vs[r * SA + ch], &vg[(size_t)r * HEAD_DIM + ch]);
        }
    };

    const int jb_end = 2 * qb + 2;
    issueKV(0, 0); cp_commit();

    float m_i[2] = { -1e30f, -1e30f };
    float l_i[2] = { 0.f, 0.f };
    float o[16][4];
    #pragma unroll
    for (int dt = 0; dt < 16; dt++)
        #pragma unroll
        for (int i = 0; i < 4; i++) o[dt][i] = 0.f;

    unsigned sQ = (unsigned)__cvta_generic_to_shared(Qs);
    unsigned qBase = sQ + ((m0 + rowoff) * SA + coloff) * 2;

    int buf = 0;
    for (int jb = 0; jb < jb_end; jb++) {
        cp_wait<0>();
        __syncthreads();
        if (jb + 1 < jb_end) issueKV(jb + 1, buf ^ 1);
        cp_commit();

        if (jb * 64 <= qb * 128 + m0 + 15) {
            unsigned sK = (unsigned)__cvta_generic_to_shared(
                              smh + Q_HH + buf * 2 * KV_HH);
            unsigned sV = sK + KV_HH * 2;
            unsigned kBase = sK + (rowoff * SA + coloff) * 2;
            unsigned vBase = sV + ((coloff + lr) * SA + (quad & 1) * 8) * 2;

            float sc[8][4];
            #pragma unroll
            for (int nt = 0; nt < 8; nt++)
                #pragma unroll
                for (int i = 0; i < 4; i++) sc[nt][i] = 0.f;

            #pragma unroll
            for (int kk = 0; kk < HEAD_DIM; kk += 16) {
                unsigned qa[4];
                ldsm4(qa, qBase + kk * 2);
                #pragma unroll
                for (int p = 0; p < 4; p++) {
                    unsigned kb[4];
                    ldsm4(kb, kBase + (p * 16 * SA + kk) * 2);
                    mma_f16(sc[p * 2],     qa, kb[0], kb[2]);
                    mma_f16(sc[p * 2 + 1], qa, kb[1], kb[3]);
                }
            }

            const int qr0 = qb * 128 + m0 + g;
            const int qr1 = qr0 + 8;
            if (jb * 64 + 63 > qr0) {
                #pragma unroll
                for (int nt = 0; nt < 8; nt++) {
                    #pragma unroll
                    for (int c = 0; c < 2; c++) {
                        int col = jb * 64 + nt * 8 + tg * 2 + c;
                        if (col > qr0) sc[nt][c]     = -1e30f;
                        if (col > qr1) sc[nt][2 + c] = -1e30f;
                    }
                }
            }

            float mx0 = -1e30f, mx1 = -1e30f;
            #pragma unroll
            for (int nt = 0; nt < 8; nt++) {
                mx0 = fmaxf(mx0, fmaxf(sc[nt][0], sc[nt][1]));
                mx1 = fmaxf(mx1, fmaxf(sc[nt][2], sc[nt][3]));
            }
            mx0 = fmaxf(mx0, __shfl_xor_sync(0xffffffffu, mx0, 1));
            mx0 = fmaxf(mx0, __shfl_xor_sync(0xffffffffu, mx0, 2));
            mx1 = fmaxf(mx1, __shfl_xor_sync(0xffffffffu, mx1, 1));
            mx1 = fmaxf(mx1, __shfl_xor_sync(0xffffffffu, mx1, 2));

            float mn0 = fmaxf(m_i[0], mx0);
            float mn1 = fmaxf(m_i[1], mx1);
            float corr0 = __expf(m_i[0] - mn0);
            float corr1 = __expf(m_i[1] - mn1);
            float ps0 = 0.f, ps1 = 0.f;
            #pragma unroll
            for (int nt = 0; nt < 8; nt++) {
                sc[nt][0] = __expf(sc[nt][0] - mn0);
                sc[nt][1] = __expf(sc[nt][1] - mn0);
                sc[nt][2] = __expf(sc[nt][2] - mn1);
                sc[nt][3] = __expf(sc[nt][3] - mn1);
                ps0 += sc[nt][0] + sc[nt][1];
                ps1 += sc[nt][2] + sc[nt][3];
            }
            ps0 += __shfl_xor_sync(0xffffffffu, ps0, 1);
            ps0 += __shfl_xor_sync(0xffffffffu, ps0, 2);
            ps1 += __shfl_xor_sync(0xffffffffu, ps1, 1);
            ps1 += __shfl_xor_sync(0xffffffffu, ps1, 2);
            l_i[0] = l_i[0] * corr0 + ps0;
            l_i[1] = l_i[1] * corr1 + ps1;
            m_i[0] = mn0;
            m_i[1] = mn1;

            #pragma unroll
            for (int dt = 0; dt < 16; dt++) {
                o[dt][0] *= corr0;
                o[dt][1] *= corr0;
                o[dt][2] *= corr1;
                o[dt][3] *= corr1;
            }

            unsigned pa[4][4];
            #pragma unroll
            for (int t = 0; t < 4; t++) {
                pa[t][0] = packh2(sc[2 * t][0],     sc[2 * t][1]);
                pa[t][1] = packh2(sc[2 * t][2],     sc[2 * t][3]);
                pa[t][2] = packh2(sc[2 * t + 1][0], sc[2 * t + 1][1]);
                pa[t][3] = packh2(sc[2 * t + 1][2], sc[2 * t + 1][3]);
            }

            #pragma unroll
            for (int t = 0; t < 4; t++) {
                #pragma unroll
                for (int p2 = 0; p2 < 8; p2++) {
                    unsigned vb[4];
                    ldsm4t(vb, vBase + (t * 16 * SA + p2 * 16) * 2);
                    mma_f16(o[p2 * 2],     pa[t], vb[0], vb[2]);
                    mma_f16(o[p2 * 2 + 1], pa[t], vb[1], vb[3]);
                }
            }
        }
        buf ^= 1;
    }

    float inv0 = 1.f / l_i[0];
    float inv1 = 1.f / l_i[1];
    int r0 = qb * 128 + m0 + g;
    int r1 = r0 + 8;
    #pragma unroll
    for (int dt = 0; dt < 16; dt++) {
        int d = dt * 8 + tg * 2;
        *(__half2*)&g_att_h[(size_t)r0 * Q_SIZE + h * HEAD_DIM + d] =
            __floats2half2_rn(o[dt][0] * inv0, o[dt][1] * inv0);
        *(__half2*)&g_att_h[(size_t)r1 * Q_SIZE + h * HEAD_DIM + d] =
            __floats2half2_rn(o[dt][2] * inv1, o[dt][3] * inv1);
    }
}

// ---------------------------------------------------------------------------
// Launch
// ---------------------------------------------------------------------------
extern "C" void kernel_launch(void* const* d_in, const int* in_sizes, int n_in,
                              void* d_out, int out_size)
{
    const float* hidden = (const float*)d_in[0];
    const float* cosT   = (const float*)d_in[1];
    const float* sinT   = (const float*)d_in[2];
    const float* W_qkv  = (const float*)d_in[7];
    const float* b_qkv  = (const float*)d_in[8];
    const float* W_o    = (const float*)d_in[9];
    float* out = (float*)d_out;

    float* qkv_p;
    __half *hid_p, *wqkv_p, *wo_p, *att_p;
    cudaGetSymbolAddress((void**)&qkv_p,  g_qkv);
    cudaGetSymbolAddress((void**)&hid_p,  g_hid_h);
    cudaGetSymbolAddress((void**)&wqkv_p, g_wqkv_t);
    cudaGetSymbolAddress((void**)&wo_p,   g_wo_t);
    cudaGetSymbolAddress((void**)&att_p,  g_att_h);

    cudaFuncSetAttribute(gemm_f16_kernel,
                         cudaFuncAttributeMaxDynamicSharedMemorySize,
                         GEMM_SMEM_BYTES);
    cudaFuncSetAttribute(flash_attn_f16_kernel,
                         cudaFuncAttributeMaxDynamicSharedMemorySize,
                         FA_SMEM_BYTES);

    // 0) fp32 -> fp16 prepass (+ weight transposes to [n][k])
    cvt_f16_kernel<<<1184, 256>>>(hidden, hid_p, S_LEN * D_MODEL / 4);
    {
        dim3 grid(QKV_COLS / 32, D_MODEL / 32);
        transpose_cvt_kernel<<<grid, dim3(32, 8)>>>(W_qkv, wqkv_p,
                                                    D_MODEL, QKV_COLS);
    }
    {
        dim3 grid(D_MODEL / 32, Q_SIZE / 32);
        transpose_cvt_kernel<<<grid, dim3(32, 8)>>>(W_o, wo_p,
                                                    Q_SIZE, D_MODEL);
    }

    // 1) QKV projection + bias (fp32 out)
    {
        dim3 grid(QKV_COLS / GBN, S_LEN / GBM);   // 20 x 16 = 320 CTAs
        gemm_f16_kernel<<<grid, 256, GEMM_SMEM_BYTES>>>(
            hid_p, wqkv_p, b_qkv, qkv_p, S_LEN, QKV_COLS, D_MODEL);
    }
    // 2) RoPE + split + q-scale (f16 out)
    rope_split_kernel<<<S_LEN, 256>>>(cosT, sinT);
    // 3) Causal GQA flash attention (f16 HMMA)
    {
        dim3 grid(S_LEN / 128, NQ_HEADS);
        flash_attn_f16_kernel<<<grid, 256, FA_SMEM_BYTES>>>();
    }
    // 4) Output projection (fp32 out)
    {
        dim3 grid(D_MODEL / GBN, S_LEN / GBM);    // 16 x 16 = 256 CTAs (1 wave)
        gemm_f16_kernel<<<grid, 256, GEMM_SMEM_BYTES>>>(
            att_p, wo_p, nullptr, out, S_LEN, D_MODEL, Q_SIZE);
    }
}